// round 5
// baseline (speedup 1.0000x reference)
#include <cuda_runtime.h>
#include <cuda_bf16.h>
#include <math.h>
#include <stdint.h>

// Problem constants
#define BB 4
#define TT 1024
#define DD 1024
#define HH 16
#define HDIM 64
#define LL 8
#define VV 50257
#define VPAD 50304
#define ROWS (BB*TT)            // 4096
#define SCALE_ATT 0.07216878364870322f  // 1/sqrt(192)

// ---------------------------------------------------------------------------
// Scratch (static device globals; no runtime allocation)
// ---------------------------------------------------------------------------
__device__ float g_x   [ (size_t)ROWS * DD     ];   // residual stream (fp32)
__device__ float g_qkv [ (size_t)ROWS * 3 * DD ];   // qkv (fp32)
__device__ float g_nll [ ROWS ];
// bf16 hi/lo split activations
__device__ __nv_bfloat16 g_hhi [ (size_t)ROWS * DD ];
__device__ __nv_bfloat16 g_hlo [ (size_t)ROWS * DD ];
__device__ __nv_bfloat16 g_yhi [ (size_t)ROWS * DD ];
__device__ __nv_bfloat16 g_ylo [ (size_t)ROWS * DD ];
__device__ __nv_bfloat16 g_mhi [ (size_t)ROWS * 4 * DD ];
__device__ __nv_bfloat16 g_mlo [ (size_t)ROWS * 4 * DD ];
__device__ __nv_bfloat16 g_xhi [ (size_t)ROWS * DD ];
__device__ __nv_bfloat16 g_xlo [ (size_t)ROWS * DD ];
// bf16 hi/lo split transposed weights ([N,K] row-major)
__device__ __nv_bfloat16 g_wqkvThi [ (size_t)LL * 3*DD * DD ];
__device__ __nv_bfloat16 g_wqkvTlo [ (size_t)LL * 3*DD * DD ];
__device__ __nv_bfloat16 g_wprojThi[ (size_t)LL * DD * DD ];
__device__ __nv_bfloat16 g_wprojTlo[ (size_t)LL * DD * DD ];
__device__ __nv_bfloat16 g_w1Thi   [ (size_t)LL * 4*DD * DD ];
__device__ __nv_bfloat16 g_w1Tlo   [ (size_t)LL * 4*DD * DD ];
__device__ __nv_bfloat16 g_w2Thi   [ (size_t)LL * DD * 4*DD ];
__device__ __nv_bfloat16 g_w2Tlo   [ (size_t)LL * DD * 4*DD ];
__device__ __nv_bfloat16 g_lmwThi  [ (size_t)VPAD * DD ];
__device__ __nv_bfloat16 g_lmwTlo  [ (size_t)VPAD * DD ];

// ---------------------------------------------------------------------------
// helpers
// ---------------------------------------------------------------------------
__device__ __forceinline__ uint32_t smem_u32(const void* p) {
    uint32_t a;
    asm("{ .reg .u64 t; cvta.to.shared.u64 t, %1; cvt.u32.u64 %0, t; }"
        : "=r"(a) : "l"(p));
    return a;
}
__device__ __forceinline__ uint32_t pack2_hi(float x, float y, float& rx, float& ry) {
    __nv_bfloat16 hx = __float2bfloat16_rn(x);
    __nv_bfloat16 hy = __float2bfloat16_rn(y);
    rx = x - __bfloat162float(hx);
    ry = y - __bfloat162float(hy);
    return (uint32_t)__bfloat16_as_ushort(hx) | ((uint32_t)__bfloat16_as_ushort(hy) << 16);
}
__device__ __forceinline__ uint32_t pack2(float x, float y) {
    __nv_bfloat16 hx = __float2bfloat16_rn(x);
    __nv_bfloat16 hy = __float2bfloat16_rn(y);
    return (uint32_t)__bfloat16_as_ushort(hx) | ((uint32_t)__bfloat16_as_ushort(hy) << 16);
}

#define MMA_BF16(d, a, b) \
    asm volatile("mma.sync.aligned.m16n8k16.row.col.f32.bf16.bf16.f32 " \
        "{%0,%1,%2,%3}, {%4,%5,%6,%7}, {%8,%9}, {%0,%1,%2,%3};" \
        : "+f"((d)[0]), "+f"((d)[1]), "+f"((d)[2]), "+f"((d)[3]) \
        : "r"((a)[0]), "r"((a)[1]), "r"((a)[2]), "r"((a)[3]), \
          "r"((b)[0]), "r"((b)[1]))

__device__ __forceinline__ void cp16(uint32_t d, const void* g) {
    asm volatile("cp.async.cg.shared.global [%0], [%1], 16;" :: "r"(d), "l"(g));
}
#define CP_COMMIT() asm volatile("cp.async.commit_group;" ::: "memory")
#define CP_WAIT0()  asm volatile("cp.async.wait_group 0;" ::: "memory")
#define CP_WAIT1()  asm volatile("cp.async.wait_group 1;" ::: "memory")

// ---------------------------------------------------------------------------
// bf16-split tensor GEMM: C = A @ Bt^T, A/B given pre-split as bf16 hi/lo.
// CTA tile 128x128, K-chunk 32, double-buffered cp.async smem, 256 threads.
// Warp tile 64x32 (2x4 warps). EPI: 0=bias->f32, 1=bias+relu->bf16 split,
// 2=bias+residual->f32. Grid: (M/128, Ntiles) so M-major waves share B in L2.
// smem per buffer: Ahi|Alo|Bhi|Blo, each 128 rows x 80B (64B payload+16B pad).
// ---------------------------------------------------------------------------
#define TILEB 10240
#define BUFB  (4*TILEB)        // 40960
#define SMEM_DYN (2*BUFB)      // 81920; epilogue Cs (128*132*4=67584) fits

template<int EPI>
__global__ __launch_bounds__(256) void hgemm_kernel(
    int M, int N, int K,
    const __nv_bfloat16* __restrict__ Ahi, const __nv_bfloat16* __restrict__ Alo,
    const __nv_bfloat16* __restrict__ Bhi, const __nv_bfloat16* __restrict__ Blo,
    const float* __restrict__ bias, const float* __restrict__ res,
    float* __restrict__ C,
    __nv_bfloat16* __restrict__ Chi, __nv_bfloat16* __restrict__ Clo)
{
    extern __shared__ __align__(128) char smem[];
    const uint32_t sb = smem_u32(smem);
    const int tid  = threadIdx.x;
    const int wid  = tid >> 5;
    const int lane = tid & 31;
    const int mbase = blockIdx.x * 128;
    const int nbase = blockIdx.y * 128;
    const int warp_m = wid & 1;
    const int warp_n = wid >> 1;
    const int g = lane >> 2;
    const int q = lane & 3;

    float acc[4][4][4];
    #pragma unroll
    for (int m = 0; m < 4; m++)
        #pragma unroll
        for (int n = 0; n < 4; n++)
            #pragma unroll
            for (int r = 0; r < 4; r++) acc[m][n][r] = 0.0f;

    const int nch = K >> 5;

    // async loader for one K-chunk into buffer at dstbase
    auto issue = [&](uint32_t dstbase, int k0) {
        #pragma unroll
        for (int i = 0; i < 8; i++) {
            const int tile = i >> 1;                 // 0:Ahi 1:Alo 2:Bhi 3:Blo
            int v   = (i & 1) * 256 + tid;           // 0..511
            int row = v >> 2, seg = v & 3;
            const __nv_bfloat16* src =
                (tile == 0) ? Ahi : (tile == 1) ? Alo : (tile == 2) ? Bhi : Blo;
            int grow = ((tile < 2) ? mbase : nbase) + row;
            cp16(dstbase + tile*TILEB + (uint32_t)row*80 + seg*16,
                 src + (size_t)grow*K + k0 + seg*8);
        }
    };

    issue(sb, 0);
    CP_COMMIT();

    for (int it = 0; it < nch; it++) {
        if (it + 1 < nch) {
            issue(sb + ((it+1) & 1) * BUFB, (it+1) << 5);
            CP_COMMIT();
            CP_WAIT1();
        } else {
            CP_WAIT0();
        }
        __syncthreads();

        const char* buf = smem + (it & 1) * BUFB;

        #pragma unroll
        for (int ks = 0; ks < 32; ks += 16) {
            uint32_t ah[4][4], al[4][4];
            #pragma unroll
            for (int m = 0; m < 4; m++) {
                int row = warp_m*64 + m*16 + g;
                const char* pa = buf + (uint32_t)row*80 + (ks + 2*q)*2;
                ah[m][0] = *(const uint32_t*)(pa);
                ah[m][1] = *(const uint32_t*)(pa + 8*80);
                ah[m][2] = *(const uint32_t*)(pa + 16);
                ah[m][3] = *(const uint32_t*)(pa + 8*80 + 16);
                const char* pl = pa + TILEB;
                al[m][0] = *(const uint32_t*)(pl);
                al[m][1] = *(const uint32_t*)(pl + 8*80);
                al[m][2] = *(const uint32_t*)(pl + 16);
                al[m][3] = *(const uint32_t*)(pl + 8*80 + 16);
            }
            uint32_t bh[4][2], bl[4][2];
            #pragma unroll
            for (int n = 0; n < 4; n++) {
                int row = warp_n*32 + n*8 + g;
                const char* pb = buf + 2*TILEB + (uint32_t)row*80 + (ks + 2*q)*2;
                bh[n][0] = *(const uint32_t*)(pb);
                bh[n][1] = *(const uint32_t*)(pb + 16);
                const char* pl = pb + TILEB;
                bl[n][0] = *(const uint32_t*)(pl);
                bl[n][1] = *(const uint32_t*)(pl + 16);
            }
            #pragma unroll
            for (int m = 0; m < 4; m++)
                #pragma unroll
                for (int n = 0; n < 4; n++) {
                    MMA_BF16(acc[m][n], ah[m], bh[n]);
                    MMA_BF16(acc[m][n], ah[m], bl[n]);
                    MMA_BF16(acc[m][n], al[m], bh[n]);
                }
        }
        __syncthreads();
    }

    // epilogue: stage through smem for coalesced writes
    float* Cs = (float*)smem;   // [128][132]
    #pragma unroll
    for (int m = 0; m < 4; m++) {
        int r0 = warp_m*64 + m*16 + g;
        #pragma unroll
        for (int n = 0; n < 4; n++) {
            int col = warp_n*32 + n*8 + 2*q;
            Cs[r0*132 + col]       = acc[m][n][0];
            Cs[r0*132 + col + 1]   = acc[m][n][1];
            Cs[(r0+8)*132 + col]   = acc[m][n][2];
            Cs[(r0+8)*132 + col+1] = acc[m][n][3];
        }
    }
    __syncthreads();

    if (EPI == 1) {
        // relu + bf16 split outputs (N always multiple of 4 here)
        #pragma unroll
        for (int i = 0; i < 16; i++) {
            int u = tid + i*256;
            int row = u >> 5, c4 = (u & 31) * 4;
            int col = nbase + c4;
            float v0 = Cs[row*132 + c4 + 0] + bias[col];
            float v1 = Cs[row*132 + c4 + 1] + bias[col+1];
            float v2 = Cs[row*132 + c4 + 2] + bias[col+2];
            float v3 = Cs[row*132 + c4 + 3] + bias[col+3];
            v0 = fmaxf(v0, 0.f); v1 = fmaxf(v1, 0.f);
            v2 = fmaxf(v2, 0.f); v3 = fmaxf(v3, 0.f);
            float r0, r1, r2, r3;
            uint2 hi, lo;
            hi.x = pack2_hi(v0, v1, r0, r1);
            hi.y = pack2_hi(v2, v3, r2, r3);
            lo.x = pack2(r0, r1); lo.y = pack2(r2, r3);
            size_t off = (size_t)(mbase+row)*N + col;
            *(uint2*)(Chi + off) = hi;
            *(uint2*)(Clo + off) = lo;
        }
    } else if ((N & 3) == 0) {
        #pragma unroll
        for (int i = 0; i < 16; i++) {
            int u = tid + i*256;
            int row = u >> 5, c4 = (u & 31) * 4;
            int col = nbase + c4;
            float v0 = Cs[row*132 + c4 + 0];
            float v1 = Cs[row*132 + c4 + 1];
            float v2 = Cs[row*132 + c4 + 2];
            float v3 = Cs[row*132 + c4 + 3];
            if (bias) { v0 += bias[col]; v1 += bias[col+1]; v2 += bias[col+2]; v3 += bias[col+3]; }
            if (EPI == 2) {
                const float4 rv = *(const float4*)(res + (size_t)(mbase+row)*N + col);
                v0 += rv.x; v1 += rv.y; v2 += rv.z; v3 += rv.w;
            }
            *(float4*)(C + (size_t)(mbase+row)*N + col) = make_float4(v0, v1, v2, v3);
        }
    } else {
        #pragma unroll
        for (int i = 0; i < 16; i++) {
            int u = tid + i*256;
            int row = u >> 5, c4 = (u & 31) * 4;
            float* crow = C + (size_t)(mbase+row)*N;
            #pragma unroll
            for (int j = 0; j < 4; j++) {
                int col = nbase + c4 + j;
                if (col < N) {
                    float v = Cs[row*132 + c4 + j];
                    if (bias) v += bias[col];
                    if (EPI == 2) v += res[(size_t)(mbase+row)*N + col];
                    crow[col] = v;
                }
            }
        }
    }
}

// ---------------------------------------------------------------------------
// Tiled transpose + bf16 split: in [K,N] -> outhi/outlo [Npad,K], zero-pad
// ---------------------------------------------------------------------------
__global__ __launch_bounds__(256) void tp_kernel(
    const float* __restrict__ in,
    __nv_bfloat16* __restrict__ outhi, __nv_bfloat16* __restrict__ outlo,
    int K, int N, int Npad, size_t inStride, size_t outStride)
{
    __shared__ float t[32][33];
    const float* ip = in + blockIdx.z * inStride;
    __nv_bfloat16* ohi = outhi + blockIdx.z * outStride;
    __nv_bfloat16* olo = outlo + blockIdx.z * outStride;
    int n0 = blockIdx.x * 32, k0 = blockIdx.y * 32;
    int tx = threadIdx.x & 31, ty = threadIdx.x >> 5;
    #pragma unroll
    for (int j = ty; j < 32; j += 8) {
        int k = k0 + j, n = n0 + tx;
        t[j][tx] = (k < K && n < N) ? ip[(size_t)k * N + n] : 0.0f;
    }
    __syncthreads();
    #pragma unroll
    for (int j = ty; j < 32; j += 8) {
        int n = n0 + j, k = k0 + tx;
        if (n < Npad && k < K) {
            float v = t[tx][j];
            __nv_bfloat16 h = __float2bfloat16_rn(v);
            __nv_bfloat16 l = __float2bfloat16_rn(v - __bfloat162float(h));
            ohi[(size_t)n * K + k] = h;
            olo[(size_t)n * K + k] = l;
        }
    }
}

// ---------------------------------------------------------------------------
// Elementwise bf16 split of a fp32 tensor (for LM-head input)
// ---------------------------------------------------------------------------
__global__ __launch_bounds__(256) void split_kernel(
    const float* __restrict__ x,
    __nv_bfloat16* __restrict__ xhi, __nv_bfloat16* __restrict__ xlo)
{
    size_t i = ((size_t)blockIdx.x * 256 + threadIdx.x) * 4;
    float4 v = *(const float4*)(x + i);
    float r0, r1, r2, r3;
    uint2 hi, lo;
    hi.x = pack2_hi(v.x, v.y, r0, r1);
    hi.y = pack2_hi(v.z, v.w, r2, r3);
    lo.x = pack2(r0, r1); lo.y = pack2(r2, r3);
    *(uint2*)(xhi + i) = hi;
    *(uint2*)(xlo + i) = lo;
}

// ---------------------------------------------------------------------------
// Embedding
// ---------------------------------------------------------------------------
__global__ __launch_bounds__(256) void embed_kernel(
    const int* __restrict__ idx, const float* __restrict__ tok,
    const float* __restrict__ pos, float* __restrict__ x)
{
    int row = blockIdx.x;
    int t   = row & (TT - 1);
    int id  = idx[row];
    const float4* tp = (const float4*)(tok + (size_t)id * DD);
    const float4* pp = (const float4*)(pos + (size_t)t  * DD);
    float4*       xp = (float4*)(x + (size_t)row * DD);
    int i = threadIdx.x;
    float4 a = tp[i], b = pp[i];
    a.x += b.x; a.y += b.y; a.z += b.z; a.w += b.w;
    xp[i] = a;
}

// ---------------------------------------------------------------------------
// LayerNorm -> bf16 hi/lo split output
// ---------------------------------------------------------------------------
__global__ __launch_bounds__(256) void ln_kernel(
    const float* __restrict__ x, const float* __restrict__ g,
    const float* __restrict__ b,
    __nv_bfloat16* __restrict__ ohi, __nv_bfloat16* __restrict__ olo)
{
    __shared__ float s1[256];
    __shared__ float s2[256];
    int row = blockIdx.x;
    int tid = threadIdx.x;
    float4 v = ((const float4*)(x + (size_t)row * DD))[tid];
    float s  = v.x + v.y + v.z + v.w;
    float ss = v.x*v.x + v.y*v.y + v.z*v.z + v.w*v.w;
    s1[tid] = s; s2[tid] = ss;
    __syncthreads();
    for (int o = 128; o > 0; o >>= 1) {
        if (tid < o) { s1[tid] += s1[tid+o]; s2[tid] += s2[tid+o]; }
        __syncthreads();
    }
    float mu   = s1[0] * (1.0f / DD);
    float var  = s2[0] * (1.0f / DD) - mu * mu;
    float rstd = rsqrtf(var + 1e-5f);
    float4 gv = ((const float4*)g)[tid];
    float4 bv = ((const float4*)b)[tid];
    float o0 = (v.x - mu) * rstd * gv.x + bv.x;
    float o1 = (v.y - mu) * rstd * gv.y + bv.y;
    float o2 = (v.z - mu) * rstd * gv.z + bv.z;
    float o3 = (v.w - mu) * rstd * gv.w + bv.w;
    float r0, r1, r2, r3;
    uint2 hi, lo;
    hi.x = pack2_hi(o0, o1, r0, r1);
    hi.y = pack2_hi(o2, o3, r2, r3);
    lo.x = pack2(r0, r1); lo.y = pack2(r2, r3);
    size_t off = (size_t)row * DD + tid * 4;
    *(uint2*)(ohi + off) = hi;
    *(uint2*)(olo + off) = lo;
}

// ---------------------------------------------------------------------------
// Fused causal attention: 4 threads per query (16 dims each), online softmax,
// score assembled via shfl. Block = 128 threads = 32 queries. Output bf16 split.
// Grid: (B*H, T/32).
// ---------------------------------------------------------------------------
__global__ __launch_bounds__(128) void attn_kernel(
    const float* __restrict__ qkv,
    __nv_bfloat16* __restrict__ yhi, __nv_bfloat16* __restrict__ ylo)
{
    const int bh  = blockIdx.x;
    const int b   = bh >> 4;
    const int h   = bh & (HH - 1);
    const int qi  = threadIdx.x >> 2;           // 0..31
    const int sub = threadIdx.x & 3;            // 0..3 (16 dims each)
    const int t   = blockIdx.y * 32 + qi;
    const int row = b * TT + t;

    __shared__ float Kt[64][HDIM];
    __shared__ float Vt[64][HDIM];

    float4 qv[4];
    {
        const float4* qp = (const float4*)(qkv + (size_t)row * (3*DD) + h * HDIM + sub * 16);
        #pragma unroll
        for (int i = 0; i < 4; i++) qv[i] = qp[i];
    }

    float4 acc[4];
    #pragma unroll
    for (int i = 0; i < 4; i++) acc[i] = make_float4(0.f, 0.f, 0.f, 0.f);
    float m = -1e30f, l = 0.0f;

    const int kmax = blockIdx.y * 32 + 31;
    // per-warp max query (8 queries per warp)
    const int warp_tmax = blockIdx.y * 32 + ((threadIdx.x >> 5) * 8 + 7);

    for (int k0 = 0; k0 <= kmax; k0 += 64) {
        {
            int r  = threadIdx.x >> 1;
            int c0 = (threadIdx.x & 1) * 32;
            const float* kp = qkv + (size_t)(b * TT + k0 + r) * (3*DD) + DD   + h * HDIM + c0;
            const float* vp = qkv + (size_t)(b * TT + k0 + r) * (3*DD) + 2*DD + h * HDIM + c0;
            #pragma unroll
            for (int i = 0; i < 8; i++) {
                *(float4*)&Kt[r][c0 + i*4] = *(const float4*)(kp + i*4);
                *(float4*)&Vt[r][c0 + i*4] = *(const float4*)(vp + i*4);
            }
        }
        __syncthreads();

        int jmaxw = warp_tmax - k0;           // uniform per warp
        if (jmaxw > 63) jmaxw = 63;
        const int jme = t - k0;               // per-thread causal bound

        for (int j = 0; j <= jmaxw; j++) {
            const float4* kr = (const float4*)&Kt[j][sub * 16];
            float s = 0.0f;
            #pragma unroll
            for (int i = 0; i < 4; i++) {
                float4 kk = kr[i];
                s += qv[i].x*kk.x + qv[i].y*kk.y + qv[i].z*kk.z + qv[i].w*kk.w;
            }
            s += __shfl_xor_sync(0xffffffffu, s, 1);
            s += __shfl_xor_sync(0xffffffffu, s, 2);
            s *= SCALE_ATT;
            if (j <= jme) {
                const float4* vr = (const float4*)&Vt[j][sub * 16];
                if (s <= m) {
                    float p = __expf(s - m);
                    l += p;
                    #pragma unroll
                    for (int i = 0; i < 4; i++) {
                        float4 vv = vr[i];
                        acc[i].x += p * vv.x; acc[i].y += p * vv.y;
                        acc[i].z += p * vv.z; acc[i].w += p * vv.w;
                    }
                } else {
                    float c = __expf(m - s);
                    m = s;
                    l = l * c + 1.0f;
                    #pragma unroll
                    for (int i = 0; i < 4; i++) {
                        float4 vv = vr[i];
                        acc[i].x = acc[i].x * c + vv.x; acc[i].y = acc[i].y * c + vv.y;
                        acc[i].z = acc[i].z * c + vv.z; acc[i].w = acc[i].w * c + vv.w;
                    }
                }
            }
        }
        __syncthreads();
    }

    float inv = 1.0f / l;
    size_t base = (size_t)row * DD + h * HDIM + sub * 16;
    #pragma unroll
    for (int i = 0; i < 4; i++) {
        float o0 = acc[i].x * inv, o1 = acc[i].y * inv;
        float o2 = acc[i].z * inv, o3 = acc[i].w * inv;
        float r0, r1, r2, r3;
        uint2 hi, lo;
        hi.x = pack2_hi(o0, o1, r0, r1);
        hi.y = pack2_hi(o2, o3, r2, r3);
        lo.x = pack2(r0, r1); lo.y = pack2(r2, r3);
        *(uint2*)(yhi + base + i*4) = hi;
        *(uint2*)(ylo + base + i*4) = lo;
    }
}

// ---------------------------------------------------------------------------
// NLL + loss
// ---------------------------------------------------------------------------
__global__ __launch_bounds__(256) void nll_kernel(
    const float* __restrict__ logits, const int* __restrict__ tgt,
    float* __restrict__ nll)
{
    __shared__ float red[256];
    int row = blockIdx.x;
    int tid = threadIdx.x;
    const float* lr = logits + (size_t)row * VV;

    float mx = -3.4e38f;
    for (int i = tid; i < VV; i += 256) mx = fmaxf(mx, lr[i]);
    red[tid] = mx; __syncthreads();
    for (int o = 128; o > 0; o >>= 1) {
        if (tid < o) red[tid] = fmaxf(red[tid], red[tid + o]);
        __syncthreads();
    }
    mx = red[0];
    __syncthreads();

    float s = 0.0f;
    for (int i = tid; i < VV; i += 256) s += __expf(lr[i] - mx);
    red[tid] = s; __syncthreads();
    for (int o = 128; o > 0; o >>= 1) {
        if (tid < o) red[tid] += red[tid + o];
        __syncthreads();
    }
    if (tid == 0) {
        float lse = mx + logf(red[0]);
        int tg = tgt[row];
        nll[row] = (tg != 0) ? (lse - lr[tg]) : 0.0f;
    }
}

__global__ __launch_bounds__(256) void loss_kernel(
    const float* __restrict__ nll, const int* __restrict__ tgt,
    float* __restrict__ out)
{
    __shared__ float s[256];
    __shared__ float c[256];
    int tid = threadIdx.x;
    float sv = 0.0f, cv = 0.0f;
    for (int i = tid; i < ROWS; i += 256) {
        sv += nll[i];
        cv += (tgt[i] != 0) ? 1.0f : 0.0f;
    }
    s[tid] = sv; c[tid] = cv; __syncthreads();
    for (int o = 128; o > 0; o >>= 1) {
        if (tid < o) { s[tid] += s[tid+o]; c[tid] += c[tid+o]; }
        __syncthreads();
    }
    if (tid == 0) out[0] = s[0] / fmaxf(c[0], 1.0f);
}

// ---------------------------------------------------------------------------
// Launcher
// ---------------------------------------------------------------------------
extern "C" void kernel_launch(void* const* d_in, const int* in_sizes, int n_in,
                              void* d_out, int out_size)
{
    const int*   idx   = (const int*)  d_in[0];
    const int*   tgt   = (const int*)  d_in[1];
    const float* tok   = (const float*)d_in[2];
    const float* pos   = (const float*)d_in[3];
    const float* ln1g  = (const float*)d_in[4];
    const float* ln1b  = (const float*)d_in[5];
    const float* wqkv  = (const float*)d_in[6];
    const float* bqkv  = (const float*)d_in[7];
    const float* wproj = (const float*)d_in[8];
    const float* bproj = (const float*)d_in[9];
    const float* ln2g  = (const float*)d_in[10];
    const float* ln2b  = (const float*)d_in[11];
    const float* w1    = (const float*)d_in[12];
    const float* b1    = (const float*)d_in[13];
    const float* w2    = (const float*)d_in[14];
    const float* b2    = (const float*)d_in[15];
    const float* lmw   = (const float*)d_in[16];

    float *px, *pqkv, *pnll;
    __nv_bfloat16 *phhi, *phlo, *pyhi, *pylo, *pmhi, *pmlo, *pxhi, *pxlo;
    __nv_bfloat16 *pwqkvhi, *pwqkvlo, *pwprojhi, *pwprojlo;
    __nv_bfloat16 *pw1hi, *pw1lo, *pw2hi, *pw2lo, *plmwhi, *plmwlo;
    cudaGetSymbolAddress((void**)&px,     g_x);
    cudaGetSymbolAddress((void**)&pqkv,   g_qkv);
    cudaGetSymbolAddress((void**)&pnll,   g_nll);
    cudaGetSymbolAddress((void**)&phhi,   g_hhi);
    cudaGetSymbolAddress((void**)&phlo,   g_hlo);
    cudaGetSymbolAddress((void**)&pyhi,   g_yhi);
    cudaGetSymbolAddress((void**)&pylo,   g_ylo);
    cudaGetSymbolAddress((void**)&pmhi,   g_mhi);
    cudaGetSymbolAddress((void**)&pmlo,   g_mlo);
    cudaGetSymbolAddress((void**)&pxhi,   g_xhi);
    cudaGetSymbolAddress((void**)&pxlo,   g_xlo);
    cudaGetSymbolAddress((void**)&pwqkvhi,  g_wqkvThi);
    cudaGetSymbolAddress((void**)&pwqkvlo,  g_wqkvTlo);
    cudaGetSymbolAddress((void**)&pwprojhi, g_wprojThi);
    cudaGetSymbolAddress((void**)&pwprojlo, g_wprojTlo);
    cudaGetSymbolAddress((void**)&pw1hi,  g_w1Thi);
    cudaGetSymbolAddress((void**)&pw1lo,  g_w1Tlo);
    cudaGetSymbolAddress((void**)&pw2hi,  g_w2Thi);
    cudaGetSymbolAddress((void**)&pw2lo,  g_w2Tlo);
    cudaGetSymbolAddress((void**)&plmwhi, g_lmwThi);
    cudaGetSymbolAddress((void**)&plmwlo, g_lmwTlo);

    cudaFuncSetAttribute((const void*)hgemm_kernel<0>,
                         cudaFuncAttributeMaxDynamicSharedMemorySize, SMEM_DYN);
    cudaFuncSetAttribute((const void*)hgemm_kernel<1>,
                         cudaFuncAttributeMaxDynamicSharedMemorySize, SMEM_DYN);
    cudaFuncSetAttribute((const void*)hgemm_kernel<2>,
                         cudaFuncAttributeMaxDynamicSharedMemorySize, SMEM_DYN);

    float* out = (float*)d_out;

    // weight transposes + bf16 split (graph-captured each launch)
    tp_kernel<<<dim3(3*DD/32, DD/32, LL), 256>>>(
        wqkv, pwqkvhi, pwqkvlo, DD, 3*DD, 3*DD, (size_t)DD*3*DD, (size_t)3*DD*DD);
    tp_kernel<<<dim3(DD/32, DD/32, LL), 256>>>(
        wproj, pwprojhi, pwprojlo, DD, DD, DD, (size_t)DD*DD, (size_t)DD*DD);
    tp_kernel<<<dim3(4*DD/32, DD/32, LL), 256>>>(
        w1, pw1hi, pw1lo, DD, 4*DD, 4*DD, (size_t)DD*4*DD, (size_t)4*DD*DD);
    tp_kernel<<<dim3(DD/32, 4*DD/32, LL), 256>>>(
        w2, pw2hi, pw2lo, 4*DD, DD, DD, (size_t)4*DD*DD, (size_t)DD*4*DD);
    tp_kernel<<<dim3(VPAD/32, DD/32, 1), 256>>>(
        lmw, plmwhi, plmwlo, DD, VV, VPAD, 0, 0);

    embed_kernel<<<ROWS, 256>>>(idx, tok, pos, px);

    for (int l = 0; l < LL; l++) {
        ln_kernel<<<ROWS, 256>>>(px, ln1g + (size_t)l*DD, ln1b + (size_t)l*DD, phhi, phlo);
        hgemm_kernel<0><<<dim3(ROWS/128, 3*DD/128), 256, SMEM_DYN>>>(
            ROWS, 3*DD, DD, phhi, phlo,
            pwqkvhi + (size_t)l*3*DD*DD, pwqkvlo + (size_t)l*3*DD*DD,
            bqkv + (size_t)l*3*DD, nullptr, pqkv, nullptr, nullptr);
        attn_kernel<<<dim3(BB*HH, TT/32), 128>>>(pqkv, pyhi, pylo);
        hgemm_kernel<2><<<dim3(ROWS/128, DD/128), 256, SMEM_DYN>>>(
            ROWS, DD, DD, pyhi, pylo,
            pwprojhi + (size_t)l*DD*DD, pwprojlo + (size_t)l*DD*DD,
            bproj + (size_t)l*DD, px, px, nullptr, nullptr);
        ln_kernel<<<ROWS, 256>>>(px, ln2g + (size_t)l*DD, ln2b + (size_t)l*DD, phhi, phlo);
        hgemm_kernel<1><<<dim3(ROWS/128, 4*DD/128), 256, SMEM_DYN>>>(
            ROWS, 4*DD, DD, phhi, phlo,
            pw1hi + (size_t)l*4*DD*DD, pw1lo + (size_t)l*4*DD*DD,
            b1 + (size_t)l*4*DD, nullptr, nullptr, pmhi, pmlo);
        hgemm_kernel<2><<<dim3(ROWS/128, DD/128), 256, SMEM_DYN>>>(
            ROWS, DD, 4*DD, pmhi, pmlo,
            pw2hi + (size_t)l*DD*4*DD, pw2lo + (size_t)l*DD*4*DD,
            b2 + (size_t)l*DD, px, px, nullptr, nullptr);
    }

    // split residual stream for LM head, then logits = x @ lm_w
    split_kernel<<<ROWS, 256>>>(px, pxhi, pxlo);
    hgemm_kernel<0><<<dim3(ROWS/128, VPAD/128), 256, SMEM_DYN>>>(
        ROWS, VV, DD, pxhi, pxlo, plmwhi, plmwlo,
        nullptr, nullptr, out, nullptr, nullptr);

    // loss
    nll_kernel<<<ROWS, 256>>>(out, tgt, pnll);
    size_t nlog = (size_t)ROWS * VV;
    if ((size_t)out_size > nlog) {
        loss_kernel<<<1, 256>>>(pnll, tgt, out + nlog);
    }
}

// round 6
// speedup vs baseline: 1.2514x; 1.2514x over previous
#include <cuda_runtime.h>
#include <cuda_bf16.h>
#include <math.h>
#include <stdint.h>

// Problem constants
#define BB 4
#define TT 1024
#define DD 1024
#define HH 16
#define HDIM 64
#define LL 8
#define VV 50257
#define VPAD 50304
#define ROWS (BB*TT)            // 4096
#define SCALE_ATT 0.07216878364870322f  // 1/sqrt(192)

// ---------------------------------------------------------------------------
// Scratch (static device globals; no runtime allocation)
// ---------------------------------------------------------------------------
__device__ float g_x   [ (size_t)ROWS * DD     ];   // residual stream (fp32)
__device__ float g_qkv [ (size_t)ROWS * 3 * DD ];   // qkv (fp32)
__device__ float g_nll [ ROWS ];
// bf16 hi/lo split activations
__device__ __nv_bfloat16 g_hhi [ (size_t)ROWS * DD ];
__device__ __nv_bfloat16 g_hlo [ (size_t)ROWS * DD ];
__device__ __nv_bfloat16 g_yhi [ (size_t)ROWS * DD ];
__device__ __nv_bfloat16 g_ylo [ (size_t)ROWS * DD ];
__device__ __nv_bfloat16 g_mhi [ (size_t)ROWS * 4 * DD ];
__device__ __nv_bfloat16 g_mlo [ (size_t)ROWS * 4 * DD ];
__device__ __nv_bfloat16 g_xhi [ (size_t)ROWS * DD ];
__device__ __nv_bfloat16 g_xlo [ (size_t)ROWS * DD ];
// bf16 hi/lo split transposed weights ([N,K] row-major)
__device__ __nv_bfloat16 g_wqkvThi [ (size_t)LL * 3*DD * DD ];
__device__ __nv_bfloat16 g_wqkvTlo [ (size_t)LL * 3*DD * DD ];
__device__ __nv_bfloat16 g_wprojThi[ (size_t)LL * DD * DD ];
__device__ __nv_bfloat16 g_wprojTlo[ (size_t)LL * DD * DD ];
__device__ __nv_bfloat16 g_w1Thi   [ (size_t)LL * 4*DD * DD ];
__device__ __nv_bfloat16 g_w1Tlo   [ (size_t)LL * 4*DD * DD ];
__device__ __nv_bfloat16 g_w2Thi   [ (size_t)LL * DD * 4*DD ];
__device__ __nv_bfloat16 g_w2Tlo   [ (size_t)LL * DD * 4*DD ];
__device__ __nv_bfloat16 g_lmwThi  [ (size_t)VPAD * DD ];
__device__ __nv_bfloat16 g_lmwTlo  [ (size_t)VPAD * DD ];

// ---------------------------------------------------------------------------
// helpers
// ---------------------------------------------------------------------------
__device__ __forceinline__ uint32_t smem_u32(const void* p) {
    uint32_t a;
    asm("{ .reg .u64 t; cvta.to.shared.u64 t, %1; cvt.u32.u64 %0, t; }"
        : "=r"(a) : "l"(p));
    return a;
}
__device__ __forceinline__ uint32_t pack2_hi(float x, float y, float& rx, float& ry) {
    __nv_bfloat16 hx = __float2bfloat16_rn(x);
    __nv_bfloat16 hy = __float2bfloat16_rn(y);
    rx = x - __bfloat162float(hx);
    ry = y - __bfloat162float(hy);
    return (uint32_t)__bfloat16_as_ushort(hx) | ((uint32_t)__bfloat16_as_ushort(hy) << 16);
}
__device__ __forceinline__ uint32_t pack2(float x, float y) {
    __nv_bfloat16 hx = __float2bfloat16_rn(x);
    __nv_bfloat16 hy = __float2bfloat16_rn(y);
    return (uint32_t)__bfloat16_as_ushort(hx) | ((uint32_t)__bfloat16_as_ushort(hy) << 16);
}

#define MMA_BF16(d, a, b) \
    asm volatile("mma.sync.aligned.m16n8k16.row.col.f32.bf16.bf16.f32 " \
        "{%0,%1,%2,%3}, {%4,%5,%6,%7}, {%8,%9}, {%0,%1,%2,%3};" \
        : "+f"((d)[0]), "+f"((d)[1]), "+f"((d)[2]), "+f"((d)[3]) \
        : "r"((a)[0]), "r"((a)[1]), "r"((a)[2]), "r"((a)[3]), \
          "r"((b)[0]), "r"((b)[1]))

#define LDSM4(r0, r1, r2, r3, addr) \
    asm volatile("ldmatrix.sync.aligned.m8n8.x4.shared.b16 {%0,%1,%2,%3}, [%4];" \
        : "=r"(r0), "=r"(r1), "=r"(r2), "=r"(r3) : "r"(addr))

__device__ __forceinline__ void cp16(uint32_t d, const void* g) {
    asm volatile("cp.async.cg.shared.global [%0], [%1], 16;" :: "r"(d), "l"(g));
}
#define CP_COMMIT() asm volatile("cp.async.commit_group;" ::: "memory")
#define CP_WAIT0()  asm volatile("cp.async.wait_group 0;" ::: "memory")
#define CP_WAIT1()  asm volatile("cp.async.wait_group 1;" ::: "memory")

// ---------------------------------------------------------------------------
// bf16-split tensor GEMM: C = A @ Bt^T, A/B pre-split bf16 hi/lo.
// CTA tile 128x128, K-chunk 32, 3-stage cp.async pipeline, 256 threads.
// Warp tile 64x32 (2x4 warps). Fragments via ldmatrix.x4 (conflict-free on
// 80B pitch). EPI: 0=bias->f32, 1=bias+relu->bf16 split, 2=bias+res->f32.
// ---------------------------------------------------------------------------
#define TILEB 10240
#define BUFB  (4*TILEB)        // 40960
#define SMEM_DYN (3*BUFB)      // 122880; epilogue Cs (128*132*4=67584) fits

template<int EPI>
__global__ __launch_bounds__(256) void hgemm_kernel(
    int M, int N, int K,
    const __nv_bfloat16* __restrict__ Ahi, const __nv_bfloat16* __restrict__ Alo,
    const __nv_bfloat16* __restrict__ Bhi, const __nv_bfloat16* __restrict__ Blo,
    const float* __restrict__ bias, const float* __restrict__ res,
    float* __restrict__ C,
    __nv_bfloat16* __restrict__ Chi, __nv_bfloat16* __restrict__ Clo)
{
    extern __shared__ __align__(128) char smem[];
    const uint32_t sb = smem_u32(smem);
    const int tid  = threadIdx.x;
    const int wid  = tid >> 5;
    const int lane = tid & 31;
    const int mbase = blockIdx.x * 128;
    const int nbase = blockIdx.y * 128;
    const int warp_m = wid & 1;
    const int warp_n = wid >> 1;
    const int g = lane >> 2;
    const int q = lane & 3;

    // ldmatrix lane-address offsets (within a buffer)
    const uint32_t aoff = (uint32_t)(warp_m*64 + (lane & 15)) * 80
                        + ((lane >> 4) & 1) * 16;
    const uint32_t boff = 2*TILEB
                        + (uint32_t)(warp_n*32 + (lane & 7) + ((lane >> 4) & 1)*8) * 80
                        + ((lane >> 3) & 1) * 16;

    float acc[4][4][4];
    #pragma unroll
    for (int m = 0; m < 4; m++)
        #pragma unroll
        for (int n = 0; n < 4; n++)
            #pragma unroll
            for (int r = 0; r < 4; r++) acc[m][n][r] = 0.0f;

    const int nch = K >> 5;

    auto issue = [&](uint32_t dstbase, int k0) {
        #pragma unroll
        for (int i = 0; i < 8; i++) {
            const int tile = i >> 1;                 // 0:Ahi 1:Alo 2:Bhi 3:Blo
            int v   = (i & 1) * 256 + tid;           // 0..511
            int row = v >> 2, seg = v & 3;
            const __nv_bfloat16* src =
                (tile == 0) ? Ahi : (tile == 1) ? Alo : (tile == 2) ? Bhi : Blo;
            int grow = ((tile < 2) ? mbase : nbase) + row;
            cp16(dstbase + tile*TILEB + (uint32_t)row*80 + seg*16,
                 src + (size_t)grow*K + k0 + seg*8);
        }
    };

    issue(sb, 0);
    CP_COMMIT();
    if (nch > 1) { issue(sb + BUFB, 32); CP_COMMIT(); }

    for (int it = 0; it < nch; it++) {
        if (it < nch - 1) { CP_WAIT1(); } else { CP_WAIT0(); }
        __syncthreads();
        // keep 2 chunks in flight: issue it+2 before computing it
        if (it + 2 < nch) {
            issue(sb + (uint32_t)((it+2) % 3) * BUFB, (it+2) << 5);
            CP_COMMIT();
        }

        const uint32_t bufu = sb + (uint32_t)(it % 3) * BUFB;

        #pragma unroll
        for (int ks = 0; ks < 32; ks += 16) {
            uint32_t ah[4][4], al[4][4], bh[4][2], bl[4][2];
            #pragma unroll
            for (int m = 0; m < 4; m++) {
                uint32_t ad = bufu + aoff + m*(16*80) + ks*2;
                LDSM4(ah[m][0], ah[m][1], ah[m][2], ah[m][3], ad);
                LDSM4(al[m][0], al[m][1], al[m][2], al[m][3], ad + TILEB);
            }
            #pragma unroll
            for (int n2 = 0; n2 < 2; n2++) {
                uint32_t bd = bufu + boff + n2*(16*80) + ks*2;
                uint32_t r0, r1, r2, r3;
                LDSM4(r0, r1, r2, r3, bd);
                bh[n2*2][0] = r0; bh[n2*2][1] = r1;
                bh[n2*2+1][0] = r2; bh[n2*2+1][1] = r3;
                LDSM4(r0, r1, r2, r3, bd + TILEB);
                bl[n2*2][0] = r0; bl[n2*2][1] = r1;
                bl[n2*2+1][0] = r2; bl[n2*2+1][1] = r3;
            }
            #pragma unroll
            for (int m = 0; m < 4; m++)
                #pragma unroll
                for (int n = 0; n < 4; n++) {
                    MMA_BF16(acc[m][n], ah[m], bh[n]);
                    MMA_BF16(acc[m][n], ah[m], bl[n]);
                    MMA_BF16(acc[m][n], al[m], bh[n]);
                }
        }
        // no trailing sync: next iteration's top sync protects buffer reuse
    }
    __syncthreads();

    // epilogue: stage through smem for coalesced writes
    float* Cs = (float*)smem;   // [128][132]
    #pragma unroll
    for (int m = 0; m < 4; m++) {
        int r0 = warp_m*64 + m*16 + g;
        #pragma unroll
        for (int n = 0; n < 4; n++) {
            int col = warp_n*32 + n*8 + 2*q;
            Cs[r0*132 + col]       = acc[m][n][0];
            Cs[r0*132 + col + 1]   = acc[m][n][1];
            Cs[(r0+8)*132 + col]   = acc[m][n][2];
            Cs[(r0+8)*132 + col+1] = acc[m][n][3];
        }
    }
    __syncthreads();

    if (EPI == 1) {
        #pragma unroll
        for (int i = 0; i < 16; i++) {
            int u = tid + i*256;
            int row = u >> 5, c4 = (u & 31) * 4;
            int col = nbase + c4;
            float v0 = Cs[row*132 + c4 + 0] + bias[col];
            float v1 = Cs[row*132 + c4 + 1] + bias[col+1];
            float v2 = Cs[row*132 + c4 + 2] + bias[col+2];
            float v3 = Cs[row*132 + c4 + 3] + bias[col+3];
            v0 = fmaxf(v0, 0.f); v1 = fmaxf(v1, 0.f);
            v2 = fmaxf(v2, 0.f); v3 = fmaxf(v3, 0.f);
            float r0, r1, r2, r3;
            uint2 hi, lo;
            hi.x = pack2_hi(v0, v1, r0, r1);
            hi.y = pack2_hi(v2, v3, r2, r3);
            lo.x = pack2(r0, r1); lo.y = pack2(r2, r3);
            size_t off = (size_t)(mbase+row)*N + col;
            *(uint2*)(Chi + off) = hi;
            *(uint2*)(Clo + off) = lo;
        }
    } else if ((N & 3) == 0) {
        #pragma unroll
        for (int i = 0; i < 16; i++) {
            int u = tid + i*256;
            int row = u >> 5, c4 = (u & 31) * 4;
            int col = nbase + c4;
            float v0 = Cs[row*132 + c4 + 0];
            float v1 = Cs[row*132 + c4 + 1];
            float v2 = Cs[row*132 + c4 + 2];
            float v3 = Cs[row*132 + c4 + 3];
            if (bias) { v0 += bias[col]; v1 += bias[col+1]; v2 += bias[col+2]; v3 += bias[col+3]; }
            if (EPI == 2) {
                const float4 rv = *(const float4*)(res + (size_t)(mbase+row)*N + col);
                v0 += rv.x; v1 += rv.y; v2 += rv.z; v3 += rv.w;
            }
            *(float4*)(C + (size_t)(mbase+row)*N + col) = make_float4(v0, v1, v2, v3);
        }
    } else {
        #pragma unroll
        for (int i = 0; i < 16; i++) {
            int u = tid + i*256;
            int row = u >> 5, c4 = (u & 31) * 4;
            float* crow = C + (size_t)(mbase+row)*N;
            #pragma unroll
            for (int j = 0; j < 4; j++) {
                int col = nbase + c4 + j;
                if (col < N) {
                    float v = Cs[row*132 + c4 + j];
                    if (bias) v += bias[col];
                    if (EPI == 2) v += res[(size_t)(mbase+row)*N + col];
                    crow[col] = v;
                }
            }
        }
    }
}

// ---------------------------------------------------------------------------
// Tiled transpose + bf16 split: in [K,N] -> outhi/outlo [Npad,K], zero-pad
// ---------------------------------------------------------------------------
__global__ __launch_bounds__(256) void tp_kernel(
    const float* __restrict__ in,
    __nv_bfloat16* __restrict__ outhi, __nv_bfloat16* __restrict__ outlo,
    int K, int N, int Npad, size_t inStride, size_t outStride)
{
    __shared__ float t[32][33];
    const float* ip = in + blockIdx.z * inStride;
    __nv_bfloat16* ohi = outhi + blockIdx.z * outStride;
    __nv_bfloat16* olo = outlo + blockIdx.z * outStride;
    int n0 = blockIdx.x * 32, k0 = blockIdx.y * 32;
    int tx = threadIdx.x & 31, ty = threadIdx.x >> 5;
    #pragma unroll
    for (int j = ty; j < 32; j += 8) {
        int k = k0 + j, n = n0 + tx;
        t[j][tx] = (k < K && n < N) ? ip[(size_t)k * N + n] : 0.0f;
    }
    __syncthreads();
    #pragma unroll
    for (int j = ty; j < 32; j += 8) {
        int n = n0 + j, k = k0 + tx;
        if (n < Npad && k < K) {
            float v = t[tx][j];
            __nv_bfloat16 h = __float2bfloat16_rn(v);
            __nv_bfloat16 l = __float2bfloat16_rn(v - __bfloat162float(h));
            ohi[(size_t)n * K + k] = h;
            olo[(size_t)n * K + k] = l;
        }
    }
}

// ---------------------------------------------------------------------------
// Elementwise bf16 split of a fp32 tensor (for LM-head input)
// ---------------------------------------------------------------------------
__global__ __launch_bounds__(256) void split_kernel(
    const float* __restrict__ x,
    __nv_bfloat16* __restrict__ xhi, __nv_bfloat16* __restrict__ xlo)
{
    size_t i = ((size_t)blockIdx.x * 256 + threadIdx.x) * 4;
    float4 v = *(const float4*)(x + i);
    float r0, r1, r2, r3;
    uint2 hi, lo;
    hi.x = pack2_hi(v.x, v.y, r0, r1);
    hi.y = pack2_hi(v.z, v.w, r2, r3);
    lo.x = pack2(r0, r1); lo.y = pack2(r2, r3);
    *(uint2*)(xhi + i) = hi;
    *(uint2*)(xlo + i) = lo;
}

// ---------------------------------------------------------------------------
// Embedding
// ---------------------------------------------------------------------------
__global__ __launch_bounds__(256) void embed_kernel(
    const int* __restrict__ idx, const float* __restrict__ tok,
    const float* __restrict__ pos, float* __restrict__ x)
{
    int row = blockIdx.x;
    int t   = row & (TT - 1);
    int id  = idx[row];
    const float4* tp = (const float4*)(tok + (size_t)id * DD);
    const float4* pp = (const float4*)(pos + (size_t)t  * DD);
    float4*       xp = (float4*)(x + (size_t)row * DD);
    int i = threadIdx.x;
    float4 a = tp[i], b = pp[i];
    a.x += b.x; a.y += b.y; a.z += b.z; a.w += b.w;
    xp[i] = a;
}

// ---------------------------------------------------------------------------
// LayerNorm -> bf16 hi/lo split output
// ---------------------------------------------------------------------------
__global__ __launch_bounds__(256) void ln_kernel(
    const float* __restrict__ x, const float* __restrict__ g,
    const float* __restrict__ b,
    __nv_bfloat16* __restrict__ ohi, __nv_bfloat16* __restrict__ olo)
{
    __shared__ float s1[256];
    __shared__ float s2[256];
    int row = blockIdx.x;
    int tid = threadIdx.x;
    float4 v = ((const float4*)(x + (size_t)row * DD))[tid];
    float s  = v.x + v.y + v.z + v.w;
    float ss = v.x*v.x + v.y*v.y + v.z*v.z + v.w*v.w;
    s1[tid] = s; s2[tid] = ss;
    __syncthreads();
    for (int o = 128; o > 0; o >>= 1) {
        if (tid < o) { s1[tid] += s1[tid+o]; s2[tid] += s2[tid+o]; }
        __syncthreads();
    }
    float mu   = s1[0] * (1.0f / DD);
    float var  = s2[0] * (1.0f / DD) - mu * mu;
    float rstd = rsqrtf(var + 1e-5f);
    float4 gv = ((const float4*)g)[tid];
    float4 bv = ((const float4*)b)[tid];
    float o0 = (v.x - mu) * rstd * gv.x + bv.x;
    float o1 = (v.y - mu) * rstd * gv.y + bv.y;
    float o2 = (v.z - mu) * rstd * gv.z + bv.z;
    float o3 = (v.w - mu) * rstd * gv.w + bv.w;
    float r0, r1, r2, r3;
    uint2 hi, lo;
    hi.x = pack2_hi(o0, o1, r0, r1);
    hi.y = pack2_hi(o2, o3, r2, r3);
    lo.x = pack2(r0, r1); lo.y = pack2(r2, r3);
    size_t off = (size_t)row * DD + tid * 4;
    *(uint2*)(ohi + off) = hi;
    *(uint2*)(olo + off) = lo;
}

// ---------------------------------------------------------------------------
// Fused causal attention: one thread per query, branchless 16-key score
// tiles with online softmax. Block = 128 threads/queries. Grid (B*H, T/128).
// Output bf16 hi/lo split.
// ---------------------------------------------------------------------------
__global__ __launch_bounds__(128) void attn_kernel(
    const float* __restrict__ qkv,
    __nv_bfloat16* __restrict__ yhi, __nv_bfloat16* __restrict__ ylo)
{
    const int bh = blockIdx.x;
    const int b  = bh >> 4;
    const int h  = bh & (HH - 1);
    const int t  = blockIdx.y * 128 + threadIdx.x;
    const int row = b * TT + t;
    const int wid = threadIdx.x >> 5;

    __shared__ float Kt[64][HDIM];
    __shared__ float Vt[64][HDIM];

    float4 qv[16];
    {
        const float4* qp = (const float4*)(qkv + (size_t)row * (3*DD) + h * HDIM);
        #pragma unroll
        for (int i = 0; i < 16; i++) qv[i] = qp[i];
    }

    float4 acc[16];
    #pragma unroll
    for (int i = 0; i < 16; i++) acc[i] = make_float4(0.f, 0.f, 0.f, 0.f);
    float m = -1e30f, l = 0.0f;

    const int kmax = blockIdx.y * 128 + 127;
    const int warp_tmax = blockIdx.y * 128 + wid * 32 + 31;

    for (int k0 = 0; k0 <= kmax; k0 += 64) {
        {
            int r  = threadIdx.x >> 1;
            int c0 = (threadIdx.x & 1) * 32;
            const float* kp = qkv + (size_t)(b * TT + k0 + r) * (3*DD) + DD   + h * HDIM + c0;
            const float* vp = qkv + (size_t)(b * TT + k0 + r) * (3*DD) + 2*DD + h * HDIM + c0;
            #pragma unroll
            for (int i = 0; i < 8; i++) {
                *(float4*)&Kt[r][c0 + i*4] = *(const float4*)(kp + i*4);
                *(float4*)&Vt[r][c0 + i*4] = *(const float4*)(vp + i*4);
            }
        }
        __syncthreads();

        int jmaxw = warp_tmax - k0; if (jmaxw > 63) jmaxw = 63;  // warp-uniform
        int jme   = t - k0;         if (jme > 63)   jme = 63;    // per-thread

        for (int jt = 0; jt <= (jmaxw >> 4); jt++) {
            if (jt*16 <= jme) {
                float sc[16];
                #pragma unroll
                for (int jj = 0; jj < 16; jj++) {
                    int j = jt*16 + jj;
                    const float4* kr = (const float4*)&Kt[j][0];
                    float s = 0.0f;
                    #pragma unroll
                    for (int i = 0; i < 16; i++) {
                        float4 kk = kr[i];
                        s += qv[i].x*kk.x + qv[i].y*kk.y + qv[i].z*kk.z + qv[i].w*kk.w;
                    }
                    sc[jj] = (j <= jme) ? s * SCALE_ATT : -1e30f;
                }
                float tmax = sc[0];
                #pragma unroll
                for (int jj = 1; jj < 16; jj++) tmax = fmaxf(tmax, sc[jj]);
                float newm = fmaxf(m, tmax);
                float cor = __expf(m - newm);
                l *= cor;
                #pragma unroll
                for (int i = 0; i < 16; i++) {
                    acc[i].x *= cor; acc[i].y *= cor;
                    acc[i].z *= cor; acc[i].w *= cor;
                }
                #pragma unroll
                for (int jj = 0; jj < 16; jj++) {
                    float p = __expf(sc[jj] - newm);
                    l += p;
                    const float4* vr = (const float4*)&Vt[jt*16 + jj][0];
                    #pragma unroll
                    for (int i = 0; i < 16; i++) {
                        float4 vv = vr[i];
                        acc[i].x += p * vv.x; acc[i].y += p * vv.y;
                        acc[i].z += p * vv.z; acc[i].w += p * vv.w;
                    }
                }
                m = newm;
            }
        }
        __syncthreads();
    }

    float inv = 1.0f / l;
    size_t base = (size_t)row * DD + h * HDIM;
    #pragma unroll
    for (int i = 0; i < 16; i++) {
        float o0 = acc[i].x * inv, o1 = acc[i].y * inv;
        float o2 = acc[i].z * inv, o3 = acc[i].w * inv;
        float r0, r1, r2, r3;
        uint2 hi, lo;
        hi.x = pack2_hi(o0, o1, r0, r1);
        hi.y = pack2_hi(o2, o3, r2, r3);
        lo.x = pack2(r0, r1); lo.y = pack2(r2, r3);
        *(uint2*)(yhi + base + i*4) = hi;
        *(uint2*)(ylo + base + i*4) = lo;
    }
}

// ---------------------------------------------------------------------------
// NLL + loss
// ---------------------------------------------------------------------------
__global__ __launch_bounds__(256) void nll_kernel(
    const float* __restrict__ logits, const int* __restrict__ tgt,
    float* __restrict__ nll)
{
    __shared__ float red[256];
    int row = blockIdx.x;
    int tid = threadIdx.x;
    const float* lr = logits + (size_t)row * VV;

    float mx = -3.4e38f;
    for (int i = tid; i < VV; i += 256) mx = fmaxf(mx, lr[i]);
    red[tid] = mx; __syncthreads();
    for (int o = 128; o > 0; o >>= 1) {
        if (tid < o) red[tid] = fmaxf(red[tid], red[tid + o]);
        __syncthreads();
    }
    mx = red[0];
    __syncthreads();

    float s = 0.0f;
    for (int i = tid; i < VV; i += 256) s += __expf(lr[i] - mx);
    red[tid] = s; __syncthreads();
    for (int o = 128; o > 0; o >>= 1) {
        if (tid < o) red[tid] += red[tid + o];
        __syncthreads();
    }
    if (tid == 0) {
        float lse = mx + logf(red[0]);
        int tg = tgt[row];
        nll[row] = (tg != 0) ? (lse - lr[tg]) : 0.0f;
    }
}

__global__ __launch_bounds__(256) void loss_kernel(
    const float* __restrict__ nll, const int* __restrict__ tgt,
    float* __restrict__ out)
{
    __shared__ float s[256];
    __shared__ float c[256];
    int tid = threadIdx.x;
    float sv = 0.0f, cv = 0.0f;
    for (int i = tid; i < ROWS; i += 256) {
        sv += nll[i];
        cv += (tgt[i] != 0) ? 1.0f : 0.0f;
    }
    s[tid] = sv; c[tid] = cv; __syncthreads();
    for (int o = 128; o > 0; o >>= 1) {
        if (tid < o) { s[tid] += s[tid+o]; c[tid] += c[tid+o]; }
        __syncthreads();
    }
    if (tid == 0) out[0] = s[0] / fmaxf(c[0], 1.0f);
}

// ---------------------------------------------------------------------------
// Launcher
// ---------------------------------------------------------------------------
extern "C" void kernel_launch(void* const* d_in, const int* in_sizes, int n_in,
                              void* d_out, int out_size)
{
    const int*   idx   = (const int*)  d_in[0];
    const int*   tgt   = (const int*)  d_in[1];
    const float* tok   = (const float*)d_in[2];
    const float* pos   = (const float*)d_in[3];
    const float* ln1g  = (const float*)d_in[4];
    const float* ln1b  = (const float*)d_in[5];
    const float* wqkv  = (const float*)d_in[6];
    const float* bqkv  = (const float*)d_in[7];
    const float* wproj = (const float*)d_in[8];
    const float* bproj = (const float*)d_in[9];
    const float* ln2g  = (const float*)d_in[10];
    const float* ln2b  = (const float*)d_in[11];
    const float* w1    = (const float*)d_in[12];
    const float* b1    = (const float*)d_in[13];
    const float* w2    = (const float*)d_in[14];
    const float* b2    = (const float*)d_in[15];
    const float* lmw   = (const float*)d_in[16];

    float *px, *pqkv, *pnll;
    __nv_bfloat16 *phhi, *phlo, *pyhi, *pylo, *pmhi, *pmlo, *pxhi, *pxlo;
    __nv_bfloat16 *pwqkvhi, *pwqkvlo, *pwprojhi, *pwprojlo;
    __nv_bfloat16 *pw1hi, *pw1lo, *pw2hi, *pw2lo, *plmwhi, *plmwlo;
    cudaGetSymbolAddress((void**)&px,     g_x);
    cudaGetSymbolAddress((void**)&pqkv,   g_qkv);
    cudaGetSymbolAddress((void**)&pnll,   g_nll);
    cudaGetSymbolAddress((void**)&phhi,   g_hhi);
    cudaGetSymbolAddress((void**)&phlo,   g_hlo);
    cudaGetSymbolAddress((void**)&pyhi,   g_yhi);
    cudaGetSymbolAddress((void**)&pylo,   g_ylo);
    cudaGetSymbolAddress((void**)&pmhi,   g_mhi);
    cudaGetSymbolAddress((void**)&pmlo,   g_mlo);
    cudaGetSymbolAddress((void**)&pxhi,   g_xhi);
    cudaGetSymbolAddress((void**)&pxlo,   g_xlo);
    cudaGetSymbolAddress((void**)&pwqkvhi,  g_wqkvThi);
    cudaGetSymbolAddress((void**)&pwqkvlo,  g_wqkvTlo);
    cudaGetSymbolAddress((void**)&pwprojhi, g_wprojThi);
    cudaGetSymbolAddress((void**)&pwprojlo, g_wprojTlo);
    cudaGetSymbolAddress((void**)&pw1hi,  g_w1Thi);
    cudaGetSymbolAddress((void**)&pw1lo,  g_w1Tlo);
    cudaGetSymbolAddress((void**)&pw2hi,  g_w2Thi);
    cudaGetSymbolAddress((void**)&pw2lo,  g_w2Tlo);
    cudaGetSymbolAddress((void**)&plmwhi, g_lmwThi);
    cudaGetSymbolAddress((void**)&plmwlo, g_lmwTlo);

    cudaFuncSetAttribute((const void*)hgemm_kernel<0>,
                         cudaFuncAttributeMaxDynamicSharedMemorySize, SMEM_DYN);
    cudaFuncSetAttribute((const void*)hgemm_kernel<1>,
                         cudaFuncAttributeMaxDynamicSharedMemorySize, SMEM_DYN);
    cudaFuncSetAttribute((const void*)hgemm_kernel<2>,
                         cudaFuncAttributeMaxDynamicSharedMemorySize, SMEM_DYN);

    float* out = (float*)d_out;

    // weight transposes + bf16 split (graph-captured each launch)
    tp_kernel<<<dim3(3*DD/32, DD/32, LL), 256>>>(
        wqkv, pwqkvhi, pwqkvlo, DD, 3*DD, 3*DD, (size_t)DD*3*DD, (size_t)3*DD*DD);
    tp_kernel<<<dim3(DD/32, DD/32, LL), 256>>>(
        wproj, pwprojhi, pwprojlo, DD, DD, DD, (size_t)DD*DD, (size_t)DD*DD);
    tp_kernel<<<dim3(4*DD/32, DD/32, LL), 256>>>(
        w1, pw1hi, pw1lo, DD, 4*DD, 4*DD, (size_t)DD*4*DD, (size_t)4*DD*DD);
    tp_kernel<<<dim3(DD/32, 4*DD/32, LL), 256>>>(
        w2, pw2hi, pw2lo, 4*DD, DD, DD, (size_t)4*DD*DD, (size_t)DD*4*DD);
    tp_kernel<<<dim3(VPAD/32, DD/32, 1), 256>>>(
        lmw, plmwhi, plmwlo, DD, VV, VPAD, 0, 0);

    embed_kernel<<<ROWS, 256>>>(idx, tok, pos, px);

    for (int l = 0; l < LL; l++) {
        ln_kernel<<<ROWS, 256>>>(px, ln1g + (size_t)l*DD, ln1b + (size_t)l*DD, phhi, phlo);
        hgemm_kernel<0><<<dim3(ROWS/128, 3*DD/128), 256, SMEM_DYN>>>(
            ROWS, 3*DD, DD, phhi, phlo,
            pwqkvhi + (size_t)l*3*DD*DD, pwqkvlo + (size_t)l*3*DD*DD,
            bqkv + (size_t)l*3*DD, nullptr, pqkv, nullptr, nullptr);
        attn_kernel<<<dim3(BB*HH, TT/128), 128>>>(pqkv, pyhi, pylo);
        hgemm_kernel<2><<<dim3(ROWS/128, DD/128), 256, SMEM_DYN>>>(
            ROWS, DD, DD, pyhi, pylo,
            pwprojhi + (size_t)l*DD*DD, pwprojlo + (size_t)l*DD*DD,
            bproj + (size_t)l*DD, px, px, nullptr, nullptr);
        ln_kernel<<<ROWS, 256>>>(px, ln2g + (size_t)l*DD, ln2b + (size_t)l*DD, phhi, phlo);
        hgemm_kernel<1><<<dim3(ROWS/128, 4*DD/128), 256, SMEM_DYN>>>(
            ROWS, 4*DD, DD, phhi, phlo,
            pw1hi + (size_t)l*4*DD*DD, pw1lo + (size_t)l*4*DD*DD,
            b1 + (size_t)l*4*DD, nullptr, nullptr, pmhi, pmlo);
        hgemm_kernel<2><<<dim3(ROWS/128, DD/128), 256, SMEM_DYN>>>(
            ROWS, DD, 4*DD, pmhi, pmlo,
            pw2hi + (size_t)l*DD*4*DD, pw2lo + (size_t)l*DD*4*DD,
            b2 + (size_t)l*DD, px, px, nullptr, nullptr);
    }

    // split residual stream for LM head, then logits = x @ lm_w
    split_kernel<<<ROWS, 256>>>(px, pxhi, pxlo);
    hgemm_kernel<0><<<dim3(ROWS/128, VPAD/128), 256, SMEM_DYN>>>(
        ROWS, VV, DD, pxhi, pxlo, plmwhi, plmwlo,
        nullptr, nullptr, out, nullptr, nullptr);

    // loss
    nll_kernel<<<ROWS, 256>>>(out, tgt, pnll);
    size_t nlog = (size_t)ROWS * VV;
    if ((size_t)out_size > nlog) {
        loss_kernel<<<1, 256>>>(pnll, tgt, out + nlog);
    }
}